// round 16
// baseline (speedup 1.0000x reference)
#include <cuda_runtime.h>
#include <cuda_fp16.h>
#include <cstdint>
#include <math.h>

#define N_TOK  4096
#define EMBED  768
#define NHEAD  12
#define DHEAD  64
#define KPATCH 256

// ---- device scratch (allocation-free: module globals) ----
__device__ __half g_tok_h[N_TOK * EMBED];        // tokens (fp16): patch out, LN in-place
__device__ __half g_xh[1024 * 1024];             // image (fp16)
__device__ __half g_wph[EMBED * KPATCH];         // patch weight (fp16)
__device__ __half g_wh[3 * EMBED * EMBED];       // qkv weight (fp16)
__device__ __half g_qh[NHEAD * N_TOK * DHEAD];   // [h, n, d]
__device__ __half g_kh[NHEAD * N_TOK * DHEAD];   // [h, n, d]
__device__ __half g_vt[NHEAD * DHEAD * N_TOK];   // [h, d, n]  (V transposed)

// ============================================================
// helpers
// ============================================================
__device__ __forceinline__ uint32_t smem_u32(const void* p) {
    uint32_t a;
    asm("{ .reg .u64 t; cvta.to.shared.u64 t, %1; cvt.u32.u64 %0, t; }"
        : "=r"(a) : "l"(p));
    return a;
}
__device__ __forceinline__ void cp16(uint32_t dst, const void* src) {
    asm volatile("cp.async.cg.shared.global [%0], [%1], 16;"
                 :: "r"(dst), "l"(src));
}
#define CP_COMMIT() asm volatile("cp.async.commit_group;" ::: "memory")
#define CP_WAIT1()  asm volatile("cp.async.wait_group 1;" ::: "memory")

// m16n8k16 fp16 mma, fp32 accumulate
__device__ __forceinline__ void mma16(float4& d, const uint32_t a[4],
                                      uint32_t b0, uint32_t b1) {
    asm volatile(
        "mma.sync.aligned.m16n8k16.row.col.f32.f16.f16.f32 "
        "{%0,%1,%2,%3}, {%4,%5,%6,%7}, {%8,%9}, {%0,%1,%2,%3};"
        : "+f"(d.x), "+f"(d.y), "+f"(d.z), "+f"(d.w)
        : "r"(a[0]), "r"(a[1]), "r"(a[2]), "r"(a[3]), "r"(b0), "r"(b1));
}
// m16n8k16 fp16 mma, fp16 accumulate
__device__ __forceinline__ void mma16h(uint32_t& d0, uint32_t& d1,
                                       const uint32_t a[4],
                                       uint32_t b0, uint32_t b1) {
    asm volatile(
        "mma.sync.aligned.m16n8k16.row.col.f16.f16.f16.f16 "
        "{%0,%1}, {%2,%3,%4,%5}, {%6,%7}, {%0,%1};"
        : "+r"(d0), "+r"(d1)
        : "r"(a[0]), "r"(a[1]), "r"(a[2]), "r"(a[3]), "r"(b0), "r"(b1));
}
#define LDSM_X4(r0, r1, r2, r3, addr) \
    asm volatile("ldmatrix.sync.aligned.m8n8.x4.shared.b16 {%0,%1,%2,%3}, [%4];" \
        : "=r"(r0), "=r"(r1), "=r"(r2), "=r"(r3) : "r"(addr))

__device__ __forceinline__ uint32_t ldh2(const __half* p) {
    return *reinterpret_cast<const uint32_t*>(p);
}
__device__ __forceinline__ void h2exp2(uint32_t& v) {
    asm("ex2.approx.f16x2 %0, %0;" : "+r"(v));
}
__device__ __forceinline__ uint32_t h2mul(uint32_t a, uint32_t b) {
    uint32_t r;
    asm("mul.f16x2 %0, %1, %2;" : "=r"(r) : "r"(a), "r"(b));
    return r;
}

// ============================================================
// converters (split for stream overlap):
//   cvt_xpw:  image (1024 blocks) + patch weight (192 blocks)
//   cvt_qw:   qkv weight (1728 blocks) — runs on side stream
// ============================================================
__global__ __launch_bounds__(256) void cvt_xpw_kernel(
    const float* __restrict__ x, const float* __restrict__ pw)
{
    int blk = blockIdx.x;
    const float* src;
    __half* dst;
    int off;
    if (blk < 1024) { src = x;  dst = g_xh;  off = blk; }
    else            { src = pw; dst = g_wph; off = blk - 1024; }
    int i = (off * 256 + threadIdx.x) * 4;
    float4 v = *(const float4*)(src + i);
    __half2* d2 = (__half2*)(dst + i);
    d2[0] = __floats2half2_rn(v.x, v.y);
    d2[1] = __floats2half2_rn(v.z, v.w);
}
__global__ __launch_bounds__(256) void cvt_qw_kernel(const float* __restrict__ qw)
{
    int i = (blockIdx.x * 256 + threadIdx.x) * 4;
    float4 v = *(const float4*)(qw + i);
    __half2* d2 = (__half2*)(g_wh + i);
    d2[0] = __floats2half2_rn(v.x, v.y);
    d2[1] = __floats2half2_rn(v.z, v.w);
}

// ============================================================
// smem geometry shared by GEMM kernels
// ============================================================
#define GPH2 72                       // smem pitch in halves (144B)
#define GT2  (128 * GPH2)
#define GEMM_SMEM (4 * GT2 * 2)       // 73728 B

// ============================================================
// Kernel 1: patch-embed GEMM, fp16 mma -> fp16 tokens directly
// ============================================================
__global__ __launch_bounds__(256, 2) void patch_mma_kernel(
    const float* __restrict__ bias)
{
    extern __shared__ __half hsm[];
    __half* ab[2] = { hsm,           hsm + GT2 };
    __half* bb[2] = { hsm + 2 * GT2, hsm + 3 * GT2 };
    const uint32_t ab_u[2] = { smem_u32(ab[0]), smem_u32(ab[1]) };
    const uint32_t bb_u[2] = { smem_u32(bb[0]), smem_u32(bb[1]) };

    const int tid = threadIdx.x, wid = tid >> 5, lane = tid & 31;
    const int lj = lane & 3, lr = lane >> 2;
    const int wm = wid >> 2, wn = wid & 3;
    const int m0 = blockIdx.y * 128, n0 = blockIdx.x * 128;

    const int aRow = ((lane >> 3) & 1) * 8 + (lane & 7);
    const int aCol = (lane >> 4) * 8;
    const int bRow = (lane >> 4) * 8 + (lane & 7);
    const int bCol = ((lane >> 3) & 1) * 8;

    float4 acc[4][4];
#pragma unroll
    for (int i = 0; i < 4; i++)
#pragma unroll
        for (int j = 0; j < 4; j++) acc[i][j] = make_float4(0.f, 0.f, 0.f, 0.f);

#define PAT_ISSUE(KT, B) do {                                                  \
    _Pragma("unroll")                                                          \
    for (int i2 = 0; i2 < 4; i2++) {                                           \
        int c = tid + i2 * 256;                                                \
        int r = c >> 3, cl = c & 7;                                            \
        int tok = m0 + r;                                                      \
        int k = (KT) + cl * 8;                                                 \
        cp16(ab_u[B] + (r * GPH2 + cl * 8) * 2,                                \
             g_xh + ((tok >> 6) * 16 + (k >> 4)) * 1024                        \
                  + (tok & 63) * 16 + (k & 15));                               \
        cp16(bb_u[B] + (r * GPH2 + cl * 8) * 2,                                \
             g_wph + (n0 + r) * KPATCH + (KT) + cl * 8);                       \
    } } while (0)

    PAT_ISSUE(0, 0);  CP_COMMIT();
    PAT_ISSUE(64, 1); CP_COMMIT();

    const int NIT = KPATCH / 64;   // 4
    for (int it = 0; it < NIT; it++) {
        const int b = it & 1;
        CP_WAIT1();
        __syncthreads();
        const uint32_t Au = ab_u[b];
        const uint32_t Bu = bb_u[b];
#pragma unroll
        for (int gc = 0; gc < 4; gc++) {
            uint32_t af[4][4];
#pragma unroll
            for (int mt = 0; mt < 4; mt++) {
                uint32_t addr = Au + (((wm * 64 + mt * 16 + aRow) * GPH2)
                                      + gc * 16 + aCol) * 2;
                LDSM_X4(af[mt][0], af[mt][1], af[mt][2], af[mt][3], addr);
            }
#pragma unroll
            for (int j = 0; j < 2; j++) {
                uint32_t b0, b1, b2, b3;
                uint32_t addr = Bu + (((wn * 32 + j * 16 + bRow) * GPH2)
                                      + gc * 16 + bCol) * 2;
                LDSM_X4(b0, b1, b2, b3, addr);
#pragma unroll
                for (int mt = 0; mt < 4; mt++) {
                    mma16(acc[mt][2 * j],     af[mt], b0, b1);
                    mma16(acc[mt][2 * j + 1], af[mt], b2, b3);
                }
            }
        }
        __syncthreads();
        if (it + 2 < NIT) PAT_ISSUE((it + 2) * 64, b);
        CP_COMMIT();
    }

    // epilogue: add bias in fp32, round once to fp16 tokens
#pragma unroll
    for (int nt = 0; nt < 4; nt++) {
        int n = n0 + wn * 32 + nt * 8 + 2 * lj;
        float b0 = bias[n], b1 = bias[n + 1];
#pragma unroll
        for (int mt = 0; mt < 4; mt++) {
            int row = m0 + wm * 64 + mt * 16 + lr;
            *(__half2*)&g_tok_h[row * EMBED + n] =
                __floats2half2_rn(acc[mt][nt].x + b0, acc[mt][nt].y + b1);
            *(__half2*)&g_tok_h[(row + 8) * EMBED + n] =
                __floats2half2_rn(acc[mt][nt].z + b0, acc[mt][nt].w + b1);
        }
    }
}

// ============================================================
// Kernel 2: LayerNorm in place, vectorized half2 (128 thr/row)
// ============================================================
__device__ __forceinline__ float block_sum128(float v) {
    __shared__ float sh[4];
    __syncthreads();
    const int lane = threadIdx.x & 31, wrp = threadIdx.x >> 5;
#pragma unroll
    for (int o = 16; o > 0; o >>= 1) v += __shfl_xor_sync(0xffffffffu, v, o);
    if (lane == 0) sh[wrp] = v;
    __syncthreads();
    if (wrp == 0) {
        v = (lane < 4) ? sh[lane] : 0.f;
#pragma unroll
        for (int o = 2; o > 0; o >>= 1) v += __shfl_xor_sync(0xffffffffu, v, o);
        if (lane == 0) sh[0] = v;
    }
    __syncthreads();
    return sh[0];
}

__global__ __launch_bounds__(128) void ln_kernel(
    const float* __restrict__ gamma, const float* __restrict__ beta)
{
    const int n = blockIdx.x;
    const int t = threadIdx.x;
    __half2* row = (__half2*)&g_tok_h[n * EMBED];   // 384 half2
    __half2 h0 = row[t], h1 = row[t + 128], h2c = row[t + 256];
    float2 f0 = __half22float2(h0);
    float2 f1 = __half22float2(h1);
    float2 f2 = __half22float2(h2c);
    float total = block_sum128(f0.x + f0.y + f1.x + f1.y + f2.x + f2.y);
    float mu = total * (1.f / EMBED);
    float d0 = f0.x - mu, d1 = f0.y - mu, d2 = f1.x - mu;
    float d3 = f1.y - mu, d4 = f2.x - mu, d5 = f2.y - mu;
    float tot2 = block_sum128(d0 * d0 + d1 * d1 + d2 * d2
                            + d3 * d3 + d4 * d4 + d5 * d5);
    float inv = rsqrtf(tot2 * (1.f / EMBED) + 1e-6f);
    float2 g0 = ((const float2*)gamma)[t];
    float2 g1 = ((const float2*)gamma)[t + 128];
    float2 g2 = ((const float2*)gamma)[t + 256];
    float2 b0 = ((const float2*)beta)[t];
    float2 b1 = ((const float2*)beta)[t + 128];
    float2 b2 = ((const float2*)beta)[t + 256];
    row[t]       = __floats2half2_rn(d0 * inv * g0.x + b0.x, d1 * inv * g0.y + b0.y);
    row[t + 128] = __floats2half2_rn(d2 * inv * g1.x + b1.x, d3 * inv * g1.y + b1.y);
    row[t + 256] = __floats2half2_rn(d4 * inv * g2.x + b2.x, d5 * inv * g2.y + b2.y);
}

// ============================================================
// Kernel 3: QKV GEMM, fp16 mma + ldmatrix, k-tile 64 (unchanged)
// ============================================================
__global__ __launch_bounds__(256, 2) void qkv_kernel()
{
    extern __shared__ __half hsm[];
    __half* ab[2] = { hsm,           hsm + GT2 };
    __half* bb[2] = { hsm + 2 * GT2, hsm + 3 * GT2 };
    const uint32_t ab_u[2] = { smem_u32(ab[0]), smem_u32(ab[1]) };
    const uint32_t bb_u[2] = { smem_u32(bb[0]), smem_u32(bb[1]) };

    const int tid = threadIdx.x, wid = tid >> 5, lane = tid & 31;
    const int lj = lane & 3, lr = lane >> 2;
    const int wm = wid >> 2, wn = wid & 3;
    const int m0 = blockIdx.y * 128, n0 = blockIdx.x * 128;

    const int aRow = ((lane >> 3) & 1) * 8 + (lane & 7);
    const int aCol = (lane >> 4) * 8;
    const int bRow = (lane >> 4) * 8 + (lane & 7);
    const int bCol = ((lane >> 3) & 1) * 8;

    float4 acc[4][4];
#pragma unroll
    for (int i = 0; i < 4; i++)
#pragma unroll
        for (int j = 0; j < 4; j++) acc[i][j] = make_float4(0.f, 0.f, 0.f, 0.f);

#define QKV_ISSUE(KT, B) do {                                                  \
    _Pragma("unroll")                                                          \
    for (int i = 0; i < 4; i++) {                                              \
        int c = tid + i * 256;                                                 \
        int r = c >> 3, cl = c & 7;                                            \
        cp16(ab_u[B] + (r * GPH2 + cl * 8) * 2,                                \
             g_tok_h + (m0 + r) * EMBED + (KT) + cl * 8);                      \
        cp16(bb_u[B] + (r * GPH2 + cl * 8) * 2,                                \
             g_wh + (n0 + r) * EMBED + (KT) + cl * 8);                         \
    } } while (0)

    QKV_ISSUE(0, 0);  CP_COMMIT();
    QKV_ISSUE(64, 1); CP_COMMIT();

    const int NIT = EMBED / 64;   // 12
    for (int it = 0; it < NIT; it++) {
        const int b = it & 1;
        CP_WAIT1();
        __syncthreads();
        const uint32_t Au = ab_u[b];
        const uint32_t Bu = bb_u[b];
#pragma unroll
        for (int gc = 0; gc < 4; gc++) {
            uint32_t af[4][4];
#pragma unroll
            for (int mt = 0; mt < 4; mt++) {
                uint32_t addr = Au + (((wm * 64 + mt * 16 + aRow) * GPH2)
                                      + gc * 16 + aCol) * 2;
                LDSM_X4(af[mt][0], af[mt][1], af[mt][2], af[mt][3], addr);
            }
#pragma unroll
            for (int j = 0; j < 2; j++) {
                uint32_t b0, b1, b2, b3;
                uint32_t addr = Bu + (((wn * 32 + j * 16 + bRow) * GPH2)
                                      + gc * 16 + bCol) * 2;
                LDSM_X4(b0, b1, b2, b3, addr);
#pragma unroll
                for (int mt = 0; mt < 4; mt++) {
                    mma16(acc[mt][2 * j],     af[mt], b0, b1);
                    mma16(acc[mt][2 * j + 1], af[mt], b2, b3);
                }
            }
        }
        __syncthreads();
        if (it + 2 < NIT) QKV_ISSUE((it + 2) * 64, b);
        CP_COMMIT();
    }

#pragma unroll
    for (int nt = 0; nt < 4; nt++) {
        int n = n0 + wn * 32 + nt * 8 + 2 * lj;
        int s = n / EMBED;
        int r = n % EMBED;
        int hh = r / DHEAD, dd = r % DHEAD;
#pragma unroll
        for (int mt = 0; mt < 4; mt++) {
            int row = m0 + wm * 64 + mt * 16 + lr;
            if (s < 2) {
                __half* dst = ((s == 0) ? g_qh : g_kh)
                            + (hh * N_TOK + row) * DHEAD + dd;
                *(__half2*)dst = __floats2half2_rn(acc[mt][nt].x, acc[mt][nt].y);
                *(__half2*)(dst + 8 * DHEAD) =
                    __floats2half2_rn(acc[mt][nt].z, acc[mt][nt].w);
            } else {
                __half* dst = g_vt + (hh * DHEAD + dd) * N_TOK + row;
                dst[0]          = __float2half(acc[mt][nt].x);
                dst[N_TOK]      = __float2half(acc[mt][nt].y);
                dst[8]          = __float2half(acc[mt][nt].z);
                dst[N_TOK + 8]  = __float2half(acc[mt][nt].w);
            }
        }
    }
}

// ============================================================
// Kernel 4: flash attention (R14 best: AQ=128, AKV=128,
// 4 warps x 2 m-tiles, 3 CTAs/SM, dynamic smem)
// ============================================================
#define AQ     128
#define AKV    128
#define KPITCH 72
#define VPITCH 136
#define KT_SZ  (AKV * KPITCH)          // 9216 halves
#define VT_SZ  (DHEAD * VPITCH)        // 8704 halves
#define BUF_SZ (KT_SZ + VT_SZ)         // 17920 halves
#define ATT_SMEM (2 * BUF_SZ * 2)      // 71680 B
#define ATH    128

__global__ __launch_bounds__(ATH, 3) void attn_kernel(float* __restrict__ out)
{
    extern __shared__ __half hsm[];
    const uint32_t base_u = smem_u32(hsm);
    const uint32_t kb_u[2] = { base_u,              base_u + BUF_SZ * 2 };
    const uint32_t vb_u[2] = { base_u + KT_SZ * 2,  base_u + (BUF_SZ + KT_SZ) * 2 };

    const int tid = threadIdx.x, wid = tid >> 5, lane = tid & 31;
    const int lj = lane & 3, lr = lane >> 2;
    const int h = blockIdx.y, q0 = blockIdx.x * AQ;

    const int bRow = (lane >> 4) * 8 + (lane & 7);
    const int bCol = ((lane >> 3) & 1) * 8;
    const uint32_t ONEH2 = 0x3C003C00u;
    const uint32_t CEXP2 = (uint32_t)__half_as_ushort(__float2half(0.180336880f))
                         * 0x00010001u;

    const __half* Kh  = g_kh + h * N_TOK * DHEAD;
    const __half* Vth = g_vt + h * DHEAD * N_TOK;

    uint32_t qa[2][4][4];
#pragma unroll
    for (int mt = 0; mt < 2; mt++) {
        const __half* Q0 = g_qh
            + (h * N_TOK + q0 + wid * 32 + mt * 16 + lr) * DHEAD;
#pragma unroll
        for (int gc = 0; gc < 4; gc++) {
            int base = gc * 16 + 2 * lj;
            qa[mt][gc][0] = h2mul(ldh2(Q0 + base),                 CEXP2);
            qa[mt][gc][1] = h2mul(ldh2(Q0 + 8 * DHEAD + base),     CEXP2);
            qa[mt][gc][2] = h2mul(ldh2(Q0 + base + 8),             CEXP2);
            qa[mt][gc][3] = h2mul(ldh2(Q0 + 8 * DHEAD + base + 8), CEXP2);
        }
    }

    float4 oacc[2][8];
#pragma unroll
    for (int mt = 0; mt < 2; mt++)
#pragma unroll
        for (int i = 0; i < 8; i++) oacc[mt][i] = make_float4(0.f, 0.f, 0.f, 0.f);
    float4 lacc[2];
    lacc[0] = make_float4(0.f, 0.f, 0.f, 0.f);
    lacc[1] = make_float4(0.f, 0.f, 0.f, 0.f);

#define ATT_ISSUE(T, B) do {                                                   \
    _Pragma("unroll")                                                          \
    for (int i = 0; i < 8; i++) {                                              \
        int c = tid + i * ATH;                                                 \
        int kr = c >> 3, kc = c & 7;                                           \
        cp16(kb_u[B] + (kr * KPITCH + kc * 8) * 2,                             \
             Kh + ((T) * AKV + kr) * DHEAD + kc * 8);                          \
        int vr = c >> 4, vc = c & 15;                                          \
        cp16(vb_u[B] + (vr * VPITCH + vc * 8) * 2,                             \
             Vth + vr * N_TOK + (T) * AKV + vc * 8);                           \
    } } while (0)

    ATT_ISSUE(0, 0); CP_COMMIT();
    ATT_ISSUE(1, 1); CP_COMMIT();

    const int NT = N_TOK / AKV;   // 32
    for (int t = 0; t < NT; t++) {
        const int b = t & 1;
        CP_WAIT1();
        __syncthreads();
        const uint32_t Ku = kb_u[b];
        const uint32_t Vu = vb_u[b];

#pragma unroll
        for (int pair = 0; pair < 8; pair++) {    // 16-kv chunk
            uint32_t pa[2][4];
#pragma unroll
            for (int mt = 0; mt < 2; mt++)
#pragma unroll
                for (int i = 0; i < 4; i++) pa[mt][i] = 0u;
#pragma unroll
            for (int gc = 0; gc < 4; gc++) {
                uint32_t k0, k1, k2, k3;
                uint32_t addr = Ku + (((pair * 16 + bRow) * KPITCH)
                                      + gc * 16 + bCol) * 2;
                LDSM_X4(k0, k1, k2, k3, addr);
#pragma unroll
                for (int mt = 0; mt < 2; mt++) {
                    mma16h(pa[mt][0], pa[mt][1], qa[mt][gc], k0, k1);
                    mma16h(pa[mt][2], pa[mt][3], qa[mt][gc], k2, k3);
                }
            }
#pragma unroll
            for (int mt = 0; mt < 2; mt++) {
                h2exp2(pa[mt][0]); h2exp2(pa[mt][1]);
                h2exp2(pa[mt][2]); h2exp2(pa[mt][3]);
            }
#pragma unroll
            for (int dtj = 0; dtj < 4; dtj++) {
                uint32_t v0, v1, v2, v3;
                uint32_t addr = Vu + (((dtj * 16 + bRow) * VPITCH)
                                      + pair * 16 + bCol) * 2;
                LDSM_X4(v0, v1, v2, v3, addr);
#pragma unroll
                for (int mt = 0; mt < 2; mt++) {
                    mma16(oacc[mt][2 * dtj],     pa[mt], v0, v1);
                    mma16(oacc[mt][2 * dtj + 1], pa[mt], v2, v3);
                }
            }
            mma16(lacc[0], pa[0], ONEH2, ONEH2);
            mma16(lacc[1], pa[1], ONEH2, ONEH2);
        }

        __syncthreads();
        if (t + 2 < NT) ATT_ISSUE(t + 2, b);
        CP_COMMIT();
    }

#pragma unroll
    for (int mt = 0; mt < 2; mt++) {
        const float inv_lo = 1.f / lacc[mt].x;
        const float inv_hi = 1.f / lacc[mt].z;
        const int row = q0 + wid * 32 + mt * 16 + lr;
        float* o0 = out + row * EMBED + h * DHEAD + 2 * lj;
        float* o8 = o0 + 8 * EMBED;
#pragma unroll
        for (int dt = 0; dt < 8; dt++) {
            *(float2*)(o0 + dt * 8) = make_float2(oacc[mt][dt].x * inv_lo,
                                                  oacc[mt][dt].y * inv_lo);
            *(float2*)(o8 + dt * 8) = make_float2(oacc[mt][dt].z * inv_hi,
                                                  oacc[mt][dt].w * inv_hi);
        }
    }
}

// ============================================================
// launch: side stream overlaps qkv-weight conversion with
// patch-embed + LN. Streams/events created lazily on the first
// (uncaptured) correctness call; record/wait during capture
// become graph edges.
// ============================================================
static cudaStream_t g_s2 = 0;
static cudaEvent_t  g_e_fork = 0, g_e_join = 0;

extern "C" void kernel_launch(void* const* d_in, const int* in_sizes, int n_in,
                              void* d_out, int out_size)
{
    const float* x  = (const float*)d_in[0];
    const float* pw = (const float*)d_in[1];
    const float* pb = (const float*)d_in[2];
    const float* lg = (const float*)d_in[3];
    const float* lb = (const float*)d_in[4];
    const float* qw = (const float*)d_in[5];
    float* out = (float*)d_out;

    if (g_s2 == 0) {
        cudaStreamCreateWithFlags(&g_s2, cudaStreamNonBlocking);
        cudaEventCreateWithFlags(&g_e_fork, cudaEventDisableTiming);
        cudaEventCreateWithFlags(&g_e_join, cudaEventDisableTiming);
        cudaFuncSetAttribute(qkv_kernel,
                             cudaFuncAttributeMaxDynamicSharedMemorySize, GEMM_SMEM);
        cudaFuncSetAttribute(patch_mma_kernel,
                             cudaFuncAttributeMaxDynamicSharedMemorySize, GEMM_SMEM);
        cudaFuncSetAttribute(attn_kernel,
                             cudaFuncAttributeMaxDynamicSharedMemorySize, ATT_SMEM);
    }

    // fork: side stream converts qkv weights while main does patch+LN
    cudaEventRecord(g_e_fork, 0);
    cudaStreamWaitEvent(g_s2, g_e_fork, 0);
    cvt_qw_kernel<<<(3 * EMBED * EMBED) / 1024, 256, 0, g_s2>>>(qw);
    cudaEventRecord(g_e_join, g_s2);

    cvt_xpw_kernel<<<1216, 256>>>(x, pw);
    patch_mma_kernel<<<dim3(EMBED / 128, N_TOK / 128), 256, GEMM_SMEM>>>(pb);
    ln_kernel<<<N_TOK, 128>>>(lg, lb);

    cudaStreamWaitEvent(0, g_e_join, 0);   // join before qkv reads g_wh
    qkv_kernel<<<dim3(2304 / 128, N_TOK / 128), 256, GEMM_SMEM>>>();
    attn_kernel<<<dim3(N_TOK / AQ, NHEAD), ATH, ATT_SMEM>>>(out);
}

// round 17
// speedup vs baseline: 1.0198x; 1.0198x over previous
#include <cuda_runtime.h>
#include <cuda_fp16.h>
#include <cstdint>
#include <math.h>

#define N_TOK  4096
#define EMBED  768
#define NHEAD  12
#define DHEAD  64
#define KPATCH 256

// ---- device scratch (allocation-free: module globals) ----
__device__ __half g_tok_h[N_TOK * EMBED];        // tokens (fp16): patch out, LN in-place
__device__ __half g_xh[1024 * 1024];             // image (fp16)
__device__ __half g_wph[EMBED * KPATCH];         // patch weight (fp16)
__device__ __half g_wh[3 * EMBED * EMBED];       // qkv weight (fp16)
__device__ __half g_qh[NHEAD * N_TOK * DHEAD];   // [h, n, d]
__device__ __half g_kh[NHEAD * N_TOK * DHEAD];   // [h, n, d]
__device__ __half g_vt[NHEAD * DHEAD * N_TOK];   // [h, d, n]  (V transposed)

// ============================================================
// helpers
// ============================================================
__device__ __forceinline__ uint32_t smem_u32(const void* p) {
    uint32_t a;
    asm("{ .reg .u64 t; cvta.to.shared.u64 t, %1; cvt.u32.u64 %0, t; }"
        : "=r"(a) : "l"(p));
    return a;
}
__device__ __forceinline__ void cp16(uint32_t dst, const void* src) {
    asm volatile("cp.async.cg.shared.global [%0], [%1], 16;"
                 :: "r"(dst), "l"(src));
}
#define CP_COMMIT() asm volatile("cp.async.commit_group;" ::: "memory")
#define CP_WAIT1()  asm volatile("cp.async.wait_group 1;" ::: "memory")

// m16n8k16 fp16 mma, fp32 accumulate
__device__ __forceinline__ void mma16(float4& d, const uint32_t a[4],
                                      uint32_t b0, uint32_t b1) {
    asm volatile(
        "mma.sync.aligned.m16n8k16.row.col.f32.f16.f16.f32 "
        "{%0,%1,%2,%3}, {%4,%5,%6,%7}, {%8,%9}, {%0,%1,%2,%3};"
        : "+f"(d.x), "+f"(d.y), "+f"(d.z), "+f"(d.w)
        : "r"(a[0]), "r"(a[1]), "r"(a[2]), "r"(a[3]), "r"(b0), "r"(b1));
}
// m16n8k16 fp16 mma, fp16 accumulate
__device__ __forceinline__ void mma16h(uint32_t& d0, uint32_t& d1,
                                       const uint32_t a[4],
                                       uint32_t b0, uint32_t b1) {
    asm volatile(
        "mma.sync.aligned.m16n8k16.row.col.f16.f16.f16.f16 "
        "{%0,%1}, {%2,%3,%4,%5}, {%6,%7}, {%0,%1};"
        : "+r"(d0), "+r"(d1)
        : "r"(a[0]), "r"(a[1]), "r"(a[2]), "r"(a[3]), "r"(b0), "r"(b1));
}
#define LDSM_X4(r0, r1, r2, r3, addr) \
    asm volatile("ldmatrix.sync.aligned.m8n8.x4.shared.b16 {%0,%1,%2,%3}, [%4];" \
        : "=r"(r0), "=r"(r1), "=r"(r2), "=r"(r3) : "r"(addr))

__device__ __forceinline__ uint32_t ldh2(const __half* p) {
    return *reinterpret_cast<const uint32_t*>(p);
}
__device__ __forceinline__ void h2exp2(uint32_t& v) {
    asm("ex2.approx.f16x2 %0, %0;" : "+r"(v));
}
__device__ __forceinline__ uint32_t h2mul(uint32_t a, uint32_t b) {
    uint32_t r;
    asm("mul.f16x2 %0, %1, %2;" : "=r"(r) : "r"(a), "r"(b));
    return r;
}

// ============================================================
// merged converter: image | patch-weight | qkv-weight  fp32 -> fp16
// ============================================================
__global__ __launch_bounds__(256) void cvt_kernel(
    const float* __restrict__ x, const float* __restrict__ pw,
    const float* __restrict__ qw)
{
    int blk = blockIdx.x;
    const float* src;
    __half* dst;
    int off;
    if (blk < 1024)      { src = x;  dst = g_xh;  off = blk; }
    else if (blk < 1216) { src = pw; dst = g_wph; off = blk - 1024; }
    else                 { src = qw; dst = g_wh;  off = blk - 1216; }
    int i = (off * 256 + threadIdx.x) * 4;
    float4 v = *(const float4*)(src + i);
    __half2* d2 = (__half2*)(dst + i);
    d2[0] = __floats2half2_rn(v.x, v.y);
    d2[1] = __floats2half2_rn(v.z, v.w);
}

// ============================================================
// smem geometry shared by GEMM kernels
// ============================================================
#define GPH2 72                       // smem pitch in halves (144B)
#define GT2  (128 * GPH2)
#define GEMM_SMEM (4 * GT2 * 2)       // 73728 B

// ============================================================
// Kernel 1: patch-embed GEMM, fp16 mma -> fp16 tokens directly
// ============================================================
__global__ __launch_bounds__(256, 2) void patch_mma_kernel(
    const float* __restrict__ bias)
{
    extern __shared__ __half hsm[];
    __half* ab[2] = { hsm,           hsm + GT2 };
    __half* bb[2] = { hsm + 2 * GT2, hsm + 3 * GT2 };
    const uint32_t ab_u[2] = { smem_u32(ab[0]), smem_u32(ab[1]) };
    const uint32_t bb_u[2] = { smem_u32(bb[0]), smem_u32(bb[1]) };

    const int tid = threadIdx.x, wid = tid >> 5, lane = tid & 31;
    const int lj = lane & 3, lr = lane >> 2;
    const int wm = wid >> 2, wn = wid & 3;
    const int m0 = blockIdx.y * 128, n0 = blockIdx.x * 128;

    const int aRow = ((lane >> 3) & 1) * 8 + (lane & 7);
    const int aCol = (lane >> 4) * 8;
    const int bRow = (lane >> 4) * 8 + (lane & 7);
    const int bCol = ((lane >> 3) & 1) * 8;

    float4 acc[4][4];
#pragma unroll
    for (int i = 0; i < 4; i++)
#pragma unroll
        for (int j = 0; j < 4; j++) acc[i][j] = make_float4(0.f, 0.f, 0.f, 0.f);

#define PAT_ISSUE(KT, B) do {                                                  \
    _Pragma("unroll")                                                          \
    for (int i2 = 0; i2 < 4; i2++) {                                           \
        int c = tid + i2 * 256;                                                \
        int r = c >> 3, cl = c & 7;                                            \
        int tok = m0 + r;                                                      \
        int k = (KT) + cl * 8;                                                 \
        cp16(ab_u[B] + (r * GPH2 + cl * 8) * 2,                                \
             g_xh + ((tok >> 6) * 16 + (k >> 4)) * 1024                        \
                  + (tok & 63) * 16 + (k & 15));                               \
        cp16(bb_u[B] + (r * GPH2 + cl * 8) * 2,                                \
             g_wph + (n0 + r) * KPATCH + (KT) + cl * 8);                       \
    } } while (0)

    PAT_ISSUE(0, 0);  CP_COMMIT();
    PAT_ISSUE(64, 1); CP_COMMIT();

    const int NIT = KPATCH / 64;   // 4
    for (int it = 0; it < NIT; it++) {
        const int b = it & 1;
        CP_WAIT1();
        __syncthreads();
        const uint32_t Au = ab_u[b];
        const uint32_t Bu = bb_u[b];
#pragma unroll
        for (int gc = 0; gc < 4; gc++) {
            uint32_t af[4][4];
#pragma unroll
            for (int mt = 0; mt < 4; mt++) {
                uint32_t addr = Au + (((wm * 64 + mt * 16 + aRow) * GPH2)
                                      + gc * 16 + aCol) * 2;
                LDSM_X4(af[mt][0], af[mt][1], af[mt][2], af[mt][3], addr);
            }
#pragma unroll
            for (int j = 0; j < 2; j++) {
                uint32_t b0, b1, b2, b3;
                uint32_t addr = Bu + (((wn * 32 + j * 16 + bRow) * GPH2)
                                      + gc * 16 + bCol) * 2;
                LDSM_X4(b0, b1, b2, b3, addr);
#pragma unroll
                for (int mt = 0; mt < 4; mt++) {
                    mma16(acc[mt][2 * j],     af[mt], b0, b1);
                    mma16(acc[mt][2 * j + 1], af[mt], b2, b3);
                }
            }
        }
        __syncthreads();
        if (it + 2 < NIT) PAT_ISSUE((it + 2) * 64, b);
        CP_COMMIT();
    }

    // epilogue: add bias in fp32, round once to fp16 tokens
#pragma unroll
    for (int nt = 0; nt < 4; nt++) {
        int n = n0 + wn * 32 + nt * 8 + 2 * lj;
        float b0 = bias[n], b1 = bias[n + 1];
#pragma unroll
        for (int mt = 0; mt < 4; mt++) {
            int row = m0 + wm * 64 + mt * 16 + lr;
            *(__half2*)&g_tok_h[row * EMBED + n] =
                __floats2half2_rn(acc[mt][nt].x + b0, acc[mt][nt].y + b1);
            *(__half2*)&g_tok_h[(row + 8) * EMBED + n] =
                __floats2half2_rn(acc[mt][nt].z + b0, acc[mt][nt].w + b1);
        }
    }
}

// ============================================================
// Kernel 2: LayerNorm in place, vectorized half2 (128 thr/row)
// ============================================================
__device__ __forceinline__ float block_sum128(float v) {
    __shared__ float sh[4];
    __syncthreads();
    const int lane = threadIdx.x & 31, wrp = threadIdx.x >> 5;
#pragma unroll
    for (int o = 16; o > 0; o >>= 1) v += __shfl_xor_sync(0xffffffffu, v, o);
    if (lane == 0) sh[wrp] = v;
    __syncthreads();
    if (wrp == 0) {
        v = (lane < 4) ? sh[lane] : 0.f;
#pragma unroll
        for (int o = 2; o > 0; o >>= 1) v += __shfl_xor_sync(0xffffffffu, v, o);
        if (lane == 0) sh[0] = v;
    }
    __syncthreads();
    return sh[0];
}

__global__ __launch_bounds__(128) void ln_kernel(
    const float* __restrict__ gamma, const float* __restrict__ beta)
{
    const int n = blockIdx.x;
    const int t = threadIdx.x;
    __half2* row = (__half2*)&g_tok_h[n * EMBED];   // 384 half2
    __half2 h0 = row[t], h1 = row[t + 128], h2c = row[t + 256];
    float2 f0 = __half22float2(h0);
    float2 f1 = __half22float2(h1);
    float2 f2 = __half22float2(h2c);
    float total = block_sum128(f0.x + f0.y + f1.x + f1.y + f2.x + f2.y);
    float mu = total * (1.f / EMBED);
    float d0 = f0.x - mu, d1 = f0.y - mu, d2 = f1.x - mu;
    float d3 = f1.y - mu, d4 = f2.x - mu, d5 = f2.y - mu;
    float tot2 = block_sum128(d0 * d0 + d1 * d1 + d2 * d2
                            + d3 * d3 + d4 * d4 + d5 * d5);
    float inv = rsqrtf(tot2 * (1.f / EMBED) + 1e-6f);
    float2 g0 = ((const float2*)gamma)[t];
    float2 g1 = ((const float2*)gamma)[t + 128];
    float2 g2 = ((const float2*)gamma)[t + 256];
    float2 b0 = ((const float2*)beta)[t];
    float2 b1 = ((const float2*)beta)[t + 128];
    float2 b2 = ((const float2*)beta)[t + 256];
    row[t]       = __floats2half2_rn(d0 * inv * g0.x + b0.x, d1 * inv * g0.y + b0.y);
    row[t + 128] = __floats2half2_rn(d2 * inv * g1.x + b1.x, d3 * inv * g1.y + b1.y);
    row[t + 256] = __floats2half2_rn(d4 * inv * g2.x + b2.x, d5 * inv * g2.y + b2.y);
}

// ============================================================
// Kernel 3: QKV GEMM, fp16 mma + ldmatrix, k-tile 64 (unchanged)
// ============================================================
__global__ __launch_bounds__(256, 2) void qkv_kernel()
{
    extern __shared__ __half hsm[];
    __half* ab[2] = { hsm,           hsm + GT2 };
    __half* bb[2] = { hsm + 2 * GT2, hsm + 3 * GT2 };
    const uint32_t ab_u[2] = { smem_u32(ab[0]), smem_u32(ab[1]) };
    const uint32_t bb_u[2] = { smem_u32(bb[0]), smem_u32(bb[1]) };

    const int tid = threadIdx.x, wid = tid >> 5, lane = tid & 31;
    const int lj = lane & 3, lr = lane >> 2;
    const int wm = wid >> 2, wn = wid & 3;
    const int m0 = blockIdx.y * 128, n0 = blockIdx.x * 128;

    const int aRow = ((lane >> 3) & 1) * 8 + (lane & 7);
    const int aCol = (lane >> 4) * 8;
    const int bRow = (lane >> 4) * 8 + (lane & 7);
    const int bCol = ((lane >> 3) & 1) * 8;

    float4 acc[4][4];
#pragma unroll
    for (int i = 0; i < 4; i++)
#pragma unroll
        for (int j = 0; j < 4; j++) acc[i][j] = make_float4(0.f, 0.f, 0.f, 0.f);

#define QKV_ISSUE(KT, B) do {                                                  \
    _Pragma("unroll")                                                          \
    for (int i = 0; i < 4; i++) {                                              \
        int c = tid + i * 256;                                                 \
        int r = c >> 3, cl = c & 7;                                            \
        cp16(ab_u[B] + (r * GPH2 + cl * 8) * 2,                                \
             g_tok_h + (m0 + r) * EMBED + (KT) + cl * 8);                      \
        cp16(bb_u[B] + (r * GPH2 + cl * 8) * 2,                                \
             g_wh + (n0 + r) * EMBED + (KT) + cl * 8);                         \
    } } while (0)

    QKV_ISSUE(0, 0);  CP_COMMIT();
    QKV_ISSUE(64, 1); CP_COMMIT();

    const int NIT = EMBED / 64;   // 12
    for (int it = 0; it < NIT; it++) {
        const int b = it & 1;
        CP_WAIT1();
        __syncthreads();
        const uint32_t Au = ab_u[b];
        const uint32_t Bu = bb_u[b];
#pragma unroll
        for (int gc = 0; gc < 4; gc++) {
            uint32_t af[4][4];
#pragma unroll
            for (int mt = 0; mt < 4; mt++) {
                uint32_t addr = Au + (((wm * 64 + mt * 16 + aRow) * GPH2)
                                      + gc * 16 + aCol) * 2;
                LDSM_X4(af[mt][0], af[mt][1], af[mt][2], af[mt][3], addr);
            }
#pragma unroll
            for (int j = 0; j < 2; j++) {
                uint32_t b0, b1, b2, b3;
                uint32_t addr = Bu + (((wn * 32 + j * 16 + bRow) * GPH2)
                                      + gc * 16 + bCol) * 2;
                LDSM_X4(b0, b1, b2, b3, addr);
#pragma unroll
                for (int mt = 0; mt < 4; mt++) {
                    mma16(acc[mt][2 * j],     af[mt], b0, b1);
                    mma16(acc[mt][2 * j + 1], af[mt], b2, b3);
                }
            }
        }
        __syncthreads();
        if (it + 2 < NIT) QKV_ISSUE((it + 2) * 64, b);
        CP_COMMIT();
    }

#pragma unroll
    for (int nt = 0; nt < 4; nt++) {
        int n = n0 + wn * 32 + nt * 8 + 2 * lj;
        int s = n / EMBED;
        int r = n % EMBED;
        int hh = r / DHEAD, dd = r % DHEAD;
#pragma unroll
        for (int mt = 0; mt < 4; mt++) {
            int row = m0 + wm * 64 + mt * 16 + lr;
            if (s < 2) {
                __half* dst = ((s == 0) ? g_qh : g_kh)
                            + (hh * N_TOK + row) * DHEAD + dd;
                *(__half2*)dst = __floats2half2_rn(acc[mt][nt].x, acc[mt][nt].y);
                *(__half2*)(dst + 8 * DHEAD) =
                    __floats2half2_rn(acc[mt][nt].z, acc[mt][nt].w);
            } else {
                __half* dst = g_vt + (hh * DHEAD + dd) * N_TOK + row;
                dst[0]          = __float2half(acc[mt][nt].x);
                dst[N_TOK]      = __float2half(acc[mt][nt].y);
                dst[8]          = __float2half(acc[mt][nt].z);
                dst[N_TOK + 8]  = __float2half(acc[mt][nt].w);
            }
        }
    }
}

// ============================================================
// Kernel 4: flash attention (best: AQ=128, AKV=128,
// 4 warps x 2 m-tiles, 3 CTAs/SM, dynamic smem)
// ============================================================
#define AQ     128
#define AKV    128
#define KPITCH 72
#define VPITCH 136
#define KT_SZ  (AKV * KPITCH)          // 9216 halves
#define VT_SZ  (DHEAD * VPITCH)        // 8704 halves
#define BUF_SZ (KT_SZ + VT_SZ)         // 17920 halves
#define ATT_SMEM (2 * BUF_SZ * 2)      // 71680 B
#define ATH    128

__global__ __launch_bounds__(ATH, 3) void attn_kernel(float* __restrict__ out)
{
    extern __shared__ __half hsm[];
    const uint32_t base_u = smem_u32(hsm);
    const uint32_t kb_u[2] = { base_u,              base_u + BUF_SZ * 2 };
    const uint32_t vb_u[2] = { base_u + KT_SZ * 2,  base_u + (BUF_SZ + KT_SZ) * 2 };

    const int tid = threadIdx.x, wid = tid >> 5, lane = tid & 31;
    const int lj = lane & 3, lr = lane >> 2;
    const int h = blockIdx.y, q0 = blockIdx.x * AQ;

    const int bRow = (lane >> 4) * 8 + (lane & 7);
    const int bCol = ((lane >> 3) & 1) * 8;
    const uint32_t ONEH2 = 0x3C003C00u;
    const uint32_t CEXP2 = (uint32_t)__half_as_ushort(__float2half(0.180336880f))
                         * 0x00010001u;

    const __half* Kh  = g_kh + h * N_TOK * DHEAD;
    const __half* Vth = g_vt + h * DHEAD * N_TOK;

    uint32_t qa[2][4][4];
#pragma unroll
    for (int mt = 0; mt < 2; mt++) {
        const __half* Q0 = g_qh
            + (h * N_TOK + q0 + wid * 32 + mt * 16 + lr) * DHEAD;
#pragma unroll
        for (int gc = 0; gc < 4; gc++) {
            int base = gc * 16 + 2 * lj;
            qa[mt][gc][0] = h2mul(ldh2(Q0 + base),                 CEXP2);
            qa[mt][gc][1] = h2mul(ldh2(Q0 + 8 * DHEAD + base),     CEXP2);
            qa[mt][gc][2] = h2mul(ldh2(Q0 + base + 8),             CEXP2);
            qa[mt][gc][3] = h2mul(ldh2(Q0 + 8 * DHEAD + base + 8), CEXP2);
        }
    }

    float4 oacc[2][8];
#pragma unroll
    for (int mt = 0; mt < 2; mt++)
#pragma unroll
        for (int i = 0; i < 8; i++) oacc[mt][i] = make_float4(0.f, 0.f, 0.f, 0.f);
    float4 lacc[2];
    lacc[0] = make_float4(0.f, 0.f, 0.f, 0.f);
    lacc[1] = make_float4(0.f, 0.f, 0.f, 0.f);

#define ATT_ISSUE(T, B) do {                                                   \
    _Pragma("unroll")                                                          \
    for (int i = 0; i < 8; i++) {                                              \
        int c = tid + i * ATH;                                                 \
        int kr = c >> 3, kc = c & 7;                                           \
        cp16(kb_u[B] + (kr * KPITCH + kc * 8) * 2,                             \
             Kh + ((T) * AKV + kr) * DHEAD + kc * 8);                          \
        int vr = c >> 4, vc = c & 15;                                          \
        cp16(vb_u[B] + (vr * VPITCH + vc * 8) * 2,                             \
             Vth + vr * N_TOK + (T) * AKV + vc * 8);                           \
    } } while (0)

    ATT_ISSUE(0, 0); CP_COMMIT();
    ATT_ISSUE(1, 1); CP_COMMIT();

    const int NT = N_TOK / AKV;   // 32
    for (int t = 0; t < NT; t++) {
        const int b = t & 1;
        CP_WAIT1();
        __syncthreads();
        const uint32_t Ku = kb_u[b];
        const uint32_t Vu = vb_u[b];

#pragma unroll
        for (int pair = 0; pair < 8; pair++) {    // 16-kv chunk
            uint32_t pa[2][4];
#pragma unroll
            for (int mt = 0; mt < 2; mt++)
#pragma unroll
                for (int i = 0; i < 4; i++) pa[mt][i] = 0u;
#pragma unroll
            for (int gc = 0; gc < 4; gc++) {
                uint32_t k0, k1, k2, k3;
                uint32_t addr = Ku + (((pair * 16 + bRow) * KPITCH)
                                      + gc * 16 + bCol) * 2;
                LDSM_X4(k0, k1, k2, k3, addr);
#pragma unroll
                for (int mt = 0; mt < 2; mt++) {
                    mma16h(pa[mt][0], pa[mt][1], qa[mt][gc], k0, k1);
                    mma16h(pa[mt][2], pa[mt][3], qa[mt][gc], k2, k3);
                }
            }
#pragma unroll
            for (int mt = 0; mt < 2; mt++) {
                h2exp2(pa[mt][0]); h2exp2(pa[mt][1]);
                h2exp2(pa[mt][2]); h2exp2(pa[mt][3]);
            }
#pragma unroll
            for (int dtj = 0; dtj < 4; dtj++) {
                uint32_t v0, v1, v2, v3;
                uint32_t addr = Vu + (((dtj * 16 + bRow) * VPITCH)
                                      + pair * 16 + bCol) * 2;
                LDSM_X4(v0, v1, v2, v3, addr);
#pragma unroll
                for (int mt = 0; mt < 2; mt++) {
                    mma16(oacc[mt][2 * dtj],     pa[mt], v0, v1);
                    mma16(oacc[mt][2 * dtj + 1], pa[mt], v2, v3);
                }
            }
            mma16(lacc[0], pa[0], ONEH2, ONEH2);
            mma16(lacc[1], pa[1], ONEH2, ONEH2);
        }

        __syncthreads();
        if (t + 2 < NT) ATT_ISSUE(t + 2, b);
        CP_COMMIT();
    }

#pragma unroll
    for (int mt = 0; mt < 2; mt++) {
        const float inv_lo = 1.f / lacc[mt].x;
        const float inv_hi = 1.f / lacc[mt].z;
        const int row = q0 + wid * 32 + mt * 16 + lr;
        float* o0 = out + row * EMBED + h * DHEAD + 2 * lj;
        float* o8 = o0 + 8 * EMBED;
#pragma unroll
        for (int dt = 0; dt < 8; dt++) {
            *(float2*)(o0 + dt * 8) = make_float2(oacc[mt][dt].x * inv_lo,
                                                  oacc[mt][dt].y * inv_lo);
            *(float2*)(o8 + dt * 8) = make_float2(oacc[mt][dt].z * inv_hi,
                                                  oacc[mt][dt].w * inv_hi);
        }
    }
}

// ============================================================
extern "C" void kernel_launch(void* const* d_in, const int* in_sizes, int n_in,
                              void* d_out, int out_size)
{
    const float* x  = (const float*)d_in[0];
    const float* pw = (const float*)d_in[1];
    const float* pb = (const float*)d_in[2];
    const float* lg = (const float*)d_in[3];
    const float* lb = (const float*)d_in[4];
    const float* qw = (const float*)d_in[5];
    float* out = (float*)d_out;

    cudaFuncSetAttribute(qkv_kernel,
                         cudaFuncAttributeMaxDynamicSharedMemorySize, GEMM_SMEM);
    cudaFuncSetAttribute(patch_mma_kernel,
                         cudaFuncAttributeMaxDynamicSharedMemorySize, GEMM_SMEM);
    cudaFuncSetAttribute(attn_kernel,
                         cudaFuncAttributeMaxDynamicSharedMemorySize, ATT_SMEM);

    cvt_kernel<<<2944, 256>>>(x, pw, qw);
    patch_mma_kernel<<<dim3(EMBED / 128, N_TOK / 128), 256, GEMM_SMEM>>>(pb);
    ln_kernel<<<N_TOK, 128>>>(lg, lb);
    qkv_kernel<<<dim3(2304 / 128, N_TOK / 128), 256, GEMM_SMEM>>>();
    attn_kernel<<<dim3(N_TOK / AQ, NHEAD), ATH, ATT_SMEM>>>(out);
}